// round 15
// baseline (speedup 1.0000x reference)
#include <cuda_runtime.h>
#include <math.h>

#define Bn 32
#define Tn 2048
#define In 512
#define Hn 512
#define Ln 4
#define Gn 2048   // 4*H

// ---------------- phase A (layer-0 xg pre-GEMM) ----------------
#define GT 256
#define TR 128
#define TK 32
#define WPAD 132
#define ZPAD 132
#define GEMM_SMEM ((2*TK*WPAD + 2*TK*ZPAD) * 4)

// ---------------- wavefront kernel (R11 configuration) ----------------
#define WTPB 512
#define WHP 512       // Whh smem pitch (broadcast loads -> no conflicts)
#define ZPITCH 516
#define PP 33         // pre pitch (bank-conflict-free gate reads)
#define XG_T 65536    // floats per (layer,t) block: 32cl * 32b * 64rows
// smem floats: Whh 64*512 | z 32*516 | pre 2*64*33 | wbuf 2*2048 | bsh 64
#define SM_WHH 0
#define SM_Z   (64*WHP)
#define SM_PRE (SM_Z + 32*ZPITCH)
#define SM_WBUF (SM_PRE + 2*64*PP)
#define SM_BSH (SM_WBUF + 2*2048)
#define WAVE_SMEM ((SM_BSH + 64) * 4)

// Static scratch
__device__ float g_xg[(size_t)Ln * Tn * XG_T];        // [l][t][cl][b][64]
__device__ float g_h[(size_t)Ln * Tn * Bn * Hn];      // [l][t][b][j]
__device__ unsigned g_flags[256];                     // [0:128) h, [128:256) xg

__global__ void init_kernel() {
  if (threadIdx.x < 256) g_flags[threadIdx.x] = 0u;
}

#define FMA2(acc, a, b) \
  asm("fma.rn.f32x2 %0, %1, %2, %0;" : "+l"(acc) : "l"(a), "l"(b))

__device__ __forceinline__ float f2sum(unsigned long long v) {
  unsigned lo = (unsigned)v, hi = (unsigned)(v >> 32);
  return __uint_as_float(lo) + __uint_as_float(hi);
}
__device__ __forceinline__ float f2lo(unsigned long long v) {
  return __uint_as_float((unsigned)v);
}
__device__ __forceinline__ float f2hi(unsigned long long v) {
  return __uint_as_float((unsigned)(v >> 32));
}
__device__ __forceinline__ unsigned long long fsplat(float x) {
  unsigned long long r;
  asm("mov.b64 %0, {%1, %1};" : "=l"(r) : "r"(__float_as_uint(x)));
  return r;
}

__device__ __forceinline__ unsigned smem_u32(const void* p) {
  return (unsigned)__cvta_generic_to_shared(p);
}

// ============ Phase A: xg[0][t][cl][b][64] = Wih0 @ x + bias (FMA2) ============
__global__ void __launch_bounds__(GT, 2) xg_gemm_kernel(
    const float* __restrict__ W,
    const float* __restrict__ bih, const float* __restrict__ bhh,
    const float* __restrict__ x)
{
  extern __shared__ float sm[];
  float* Ws = sm;
  float* Zs = sm + 2 * TK * WPAD;

  const int tid = threadIdx.x;
  const int t0 = blockIdx.x * 4;
  const int r0 = blockIdx.y * TR;
  const int trow = tid >> 4;
  const int tcol = tid & 15;

  // packed accumulators: 8 rows x 4 column-pairs
  unsigned long long accp[8][4];
#pragma unroll
  for (int i = 0; i < 8; i++)
#pragma unroll
    for (int j = 0; j < 4; j++) accp[i][j] = 0ull;

  float4 wr[4], zr[4];

  auto ldg_chunk = [&](int kc) {
#pragma unroll
    for (int j = 0; j < 4; j++) {
      int idx = tid * 4 + j;
      int row = idx >> 3, kq = idx & 7;
      wr[j] = *reinterpret_cast<const float4*>(W + (size_t)(r0 + row) * In + kc + kq * 4);
    }
#pragma unroll
    for (int j = 0; j < 4; j++) {
      int idx = tid * 4 + j;
      int ki = idx & 7, tt = (idx >> 3) & 3, b = idx >> 5;
      zr[j] = *reinterpret_cast<const float4*>(x + ((size_t)b * Tn + t0 + tt) * In + kc + ki * 4);
    }
  };

  auto sts_chunk = [&](int buf) {
    float* Wb = Ws + buf * TK * WPAD;
    float* Zb = Zs + buf * TK * ZPAD;
#pragma unroll
    for (int j = 0; j < 4; j++) {
      int idx = tid * 4 + j;
      int row = idx >> 3, kq = idx & 7;
      Wb[(kq * 4 + 0) * WPAD + row] = wr[j].x;
      Wb[(kq * 4 + 1) * WPAD + row] = wr[j].y;
      Wb[(kq * 4 + 2) * WPAD + row] = wr[j].z;
      Wb[(kq * 4 + 3) * WPAD + row] = wr[j].w;
    }
#pragma unroll
    for (int j = 0; j < 4; j++) {
      int idx = tid * 4 + j;
      int ki = idx & 7, tt = (idx >> 3) & 3, b = idx >> 5;
      Zb[(ki * 4 + 0) * ZPAD + tt * 32 + b] = zr[j].x;
      Zb[(ki * 4 + 1) * ZPAD + tt * 32 + b] = zr[j].y;
      Zb[(ki * 4 + 2) * ZPAD + tt * 32 + b] = zr[j].z;
      Zb[(ki * 4 + 3) * ZPAD + tt * 32 + b] = zr[j].w;
    }
  };

  auto compute = [&](int buf) {
    const float* Wb = Ws + buf * TK * WPAD;
    const float* Zb = Zs + buf * TK * ZPAD;
#pragma unroll 4
    for (int kk = 0; kk < TK; kk++) {
      float4 wa = *reinterpret_cast<const float4*>(Wb + kk * WPAD + trow * 8);
      float4 wb2 = *reinterpret_cast<const float4*>(Wb + kk * WPAD + trow * 8 + 4);
      ulonglong2 zA = *reinterpret_cast<const ulonglong2*>(Zb + kk * ZPAD + tcol * 8);
      ulonglong2 zB = *reinterpret_cast<const ulonglong2*>(Zb + kk * ZPAD + tcol * 8 + 4);
      float w8[8] = {wa.x, wa.y, wa.z, wa.w, wb2.x, wb2.y, wb2.z, wb2.w};
      unsigned long long zp0 = zA.x, zp1 = zA.y, zp2 = zB.x, zp3 = zB.y;
#pragma unroll
      for (int i = 0; i < 8; i++) {
        unsigned long long wp = fsplat(w8[i]);
        FMA2(accp[i][0], wp, zp0);
        FMA2(accp[i][1], wp, zp1);
        FMA2(accp[i][2], wp, zp2);
        FMA2(accp[i][3], wp, zp3);
      }
    }
  };

  const int NCH = In / TK;
  ldg_chunk(0);
  sts_chunk(0);
  __syncthreads();
  ldg_chunk(TK);
  for (int c = 0; c < NCH; c++) {
    int buf = c & 1;
    if (c + 1 < NCH) sts_chunk(buf ^ 1);
    if (c + 2 < NCH) ldg_chunk((c + 2) * TK);
    compute(buf);
    __syncthreads();
  }

  // epilogue: [cl][b][64] layout (scatter; phase A runs once)
#pragma unroll
  for (int i = 0; i < 8; i++) {
    int row = r0 + trow * 8 + i;
    float bv = __ldg(bih + row) + __ldg(bhh + row);
    int tt = tcol >> 2;
    int b0 = (tcol & 3) * 8;
    int q = row >> 9, rem = row & 511;
    int clr = rem >> 4, ur = rem & 15;
    float* dst = g_xg + (size_t)(t0 + tt) * XG_T + clr * 2048 + (q * 16 + ur);
#pragma unroll
    for (int j = 0; j < 4; j++) {
      dst[(b0 + 2 * j + 0) * 64] = f2lo(accp[i][j]) + bv;
      dst[(b0 + 2 * j + 1) * 64] = f2hi(accp[i][j]) + bv;
    }
  }
}

__device__ __forceinline__ float fsigm(float v) {
  return __fdividef(1.f, 1.f + __expf(-v));
}
// overflow-safe fast tanh (clamp; avoids -inf/inf NaN)
__device__ __forceinline__ float ftanh(float v) {
  v = fminf(15.f, fmaxf(-15.f, v));
  float e = __expf(-2.f * v);
  return __fdividef(1.f - e, 1.f + e);
}

// ============ Wavefront: 4 layer-teams x 32 CTAs, persistent (R11) ============
__global__ void __launch_bounds__(WTPB, 1) lstm_wave_kernel(
    const float* __restrict__ h0, const float* __restrict__ c0,
    const float* __restrict__ w_ih, const float* __restrict__ w_hh,
    const float* __restrict__ b_ih, const float* __restrict__ b_hh,
    float* __restrict__ out)
{
  extern __shared__ float smem[];
  float* Wsh = smem + SM_WHH;            // [64][512]
  float* zsh = smem + SM_Z;              // [32][516]  z[b][j]
  float* pre = smem + SM_PRE;            // [2][64][33]
  float* wbuf = smem + SM_WBUF;          // [2][64][32] Wih chunk ring
  float* bsh = smem + SM_BSH;            // [64]
  const unsigned wbuf_u32 = smem_u32(wbuf);

  const int tid = threadIdx.x;
  const int ct = blockIdx.x;
  const int team = ct >> 5;              // layer
  const int cl = ct & 31;
  // shared GEMM mapping (rec + xg)
  const int kh = tid >> 8;               // K-half
  const int rg = (tid >> 4) & 15;        // rows rg, +16, +32, +48
  const int bg = tid & 15;               // batches bg, bg+16
  // gates mapping: one (unit, batch) per thread
  const int u = tid & 15;                // unit 0..15
  const int bw = tid >> 4;               // batch 0..31
  const int unit = cl * 16 + u;

  // load Whh slice
  const float* Whh = w_hh + (size_t)team * Gn * Hn;
  for (int idx = tid; idx < 64 * 128; idx += WTPB) {
    int rr = idx >> 7, kk = idx & 127;
    int q = rr >> 4, uu = rr & 15;
    int grb = q * Hn + cl * 16 + uu;
    *reinterpret_cast<float4*>(Wsh + rr * WHP + kk * 4) =
        *reinterpret_cast<const float4*>(Whh + (size_t)grb * Hn + kk * 4);
  }
  float c = c0[(size_t)team * Bn * Hn + (size_t)bw * Hn + unit];

  const float* WihN = w_ih + (size_t)(team + 1) * Gn * In;
  if (team < 3 && tid < 64) {
    int grow = (tid >> 4) * Hn + cl * 16 + (tid & 15);
    bsh[tid] = __ldg(b_ih + (size_t)(team + 1) * Gn + grow) +
               __ldg(b_hh + (size_t)(team + 1) * Gn + grow);
  }

  unsigned* hfl = g_flags + team * 32;
  unsigned* xflp = g_flags + 128 + (team - 1) * 32 + cl;
  unsigned* my_hfl = g_flags + ct;
  unsigned* my_xfl = g_flags + 128 + ct;

  // one 8KB interleaved chunk: 64 rows x (16 floats of each K-half)
  auto issue_chunk = [&](int cidx) {
    int row = tid >> 3;
    int half = (tid >> 2) & 1;
    int f4 = tid & 3;
    int grow = (row >> 4) * Hn + cl * 16 + (row & 15);
    const char* src = reinterpret_cast<const char*>(
        WihN + (size_t)grow * In + half * 256 + cidx * 16 + f4 * 4);
    unsigned dst = wbuf_u32 +
        (unsigned)(((cidx & 1) * 2048 + row * 32 + half * 16 + f4 * 4) * 4);
    asm volatile("cp.async.cg.shared.global [%0], [%1], 16;" :: "r"(dst), "l"(src));
    asm volatile("cp.async.commit_group;" ::: "memory");
  };

  // stream xg[team+1][tt] from current z (register-accumulated)
  auto xg_stream = [&](int tt) {
    unsigned long long ax[4][2];
#pragma unroll
    for (int i = 0; i < 4; i++) { ax[i][0] = 0ull; ax[i][1] = 0ull; }
#pragma unroll 1
    for (int cc = 0; cc < 16; cc++) {
      asm volatile("cp.async.wait_group 0;" ::: "memory");
      __syncthreads();                   // chunk cc visible; compute(cc-1) done
      if (cc + 1 < 16) issue_chunk(cc + 1);
      const float* wc = wbuf + (cc & 1) * 2048 + kh * 16;
      const float* zp0 = zsh + bg * ZPITCH + kh * 256 + cc * 16;
      const float* zp1 = zp0 + 16 * ZPITCH;
#pragma unroll
      for (int j = 0; j < 16; j += 4) {
        ulonglong2 z0 = *reinterpret_cast<const ulonglong2*>(zp0 + j);
        ulonglong2 z1 = *reinterpret_cast<const ulonglong2*>(zp1 + j);
#pragma unroll
        for (int i = 0; i < 4; i++) {
          ulonglong2 w = *reinterpret_cast<const ulonglong2*>(wc + (rg + 16 * i) * 32 + j);
          FMA2(ax[i][0], w.x, z0.x); FMA2(ax[i][0], w.y, z0.y);
          FMA2(ax[i][1], w.x, z1.x); FMA2(ax[i][1], w.y, z1.y);
        }
      }
    }
#pragma unroll
    for (int i = 0; i < 4; i++) {
      pre[(kh * 64 + rg + 16 * i) * PP + bg] = f2sum(ax[i][0]);
      pre[(kh * 64 + rg + 16 * i) * PP + bg + 16] = f2sum(ax[i][1]);
    }
    __syncthreads();
    {
      int b = tid >> 4, r4 = (tid & 15) * 4;
      float4 o;
      float* op = reinterpret_cast<float*>(&o);
#pragma unroll
      for (int i = 0; i < 4; i++)
        op[i] = pre[(r4 + i) * PP + b] + pre[(64 + r4 + i) * PP + b] + bsh[r4 + i];
      size_t xbase = ((size_t)(team + 1) * Tn + tt) * XG_T + cl * 2048;
      __stcg(reinterpret_cast<float4*>(g_xg + xbase + b * 64 + r4), o);
    }
  };

  float xv0, xv1, xv2, xv3;

  for (int t = 0; t < Tn; t++) {
    // ---- wait: own-team h flags >= t; upstream xg flag >= t+1
    if (t > 0 || team > 0) {
      if (tid < 32) {
        bool ok;
        do {
          ok = true;
          if (t > 0) {
            unsigned v;
            asm volatile("ld.relaxed.gpu.global.b32 %0, [%1];"
                         : "=r"(v) : "l"(hfl + tid) : "memory");
            ok &= (v >= (unsigned)t);
          }
          if (team > 0) {
            unsigned v2;
            asm volatile("ld.relaxed.gpu.global.b32 %0, [%1];"
                         : "=r"(v2) : "l"(xflp) : "memory");
            ok &= (v2 >= (unsigned)(t + 1));
          }
        } while (!__all_sync(0xffffffffu, ok));
        asm volatile("fence.acq_rel.gpu;" ::: "memory");
      }
      __syncthreads();
    }

    // ---- prologue: prefetch first Wih chunk (hidden under stage+rec+gates)
    if (team < 3 && t >= 1) issue_chunk(0);

    // ---- stage z[b][j] = h_{t-1} (pure coalesced copy)
    {
      const float4* h4 = (t == 0)
          ? reinterpret_cast<const float4*>(h0 + (size_t)team * Bn * Hn)
          : reinterpret_cast<const float4*>(
                g_h + ((size_t)team * Tn + (t - 1)) * Bn * Hn);
#pragma unroll
      for (int i = 0; i < 8; i++) {
        int idx = tid + i * WTPB;
        int b = idx >> 7, jq = idx & 127;
        float4 v = __ldcg(h4 + idx);
        *reinterpret_cast<float4*>(zsh + b * ZPITCH + jq * 4) = v;
      }
    }
    {
      const float* xp = g_xg + ((size_t)team * Tn + t) * XG_T + cl * 2048 + bw * 64 + u;
      xv0 = __ldcg(xp);
      xv1 = __ldcg(xp + 16);
      xv2 = __ldcg(xp + 32);
      xv3 = __ldcg(xp + 48);
    }
    __syncthreads();

    // ---- rec GEMM (f32x2): 4 rows x 2 batches x 256 K per thread
    {
      const float* wr = Wsh + rg * WHP + kh * 256;
      const float* zp = zsh + bg * ZPITCH + kh * 256;
      unsigned long long acc[4][2];
#pragma unroll
      for (int i = 0; i < 4; i++) { acc[i][0] = 0ull; acc[i][1] = 0ull; }
#pragma unroll 4
      for (int k = 0; k < 256; k += 4) {
        ulonglong2 z0 = *reinterpret_cast<const ulonglong2*>(zp + k);
        ulonglong2 z1 = *reinterpret_cast<const ulonglong2*>(zp + 16 * ZPITCH + k);
#pragma unroll
        for (int i = 0; i < 4; i++) {
          ulonglong2 w = *reinterpret_cast<const ulonglong2*>(wr + i * 16 * WHP + k);
          FMA2(acc[i][0], w.x, z0.x); FMA2(acc[i][0], w.y, z0.y);
          FMA2(acc[i][1], w.x, z1.x); FMA2(acc[i][1], w.y, z1.y);
        }
      }
#pragma unroll
      for (int i = 0; i < 4; i++) {
        pre[(kh * 64 + rg + 16 * i) * PP + bg] = f2sum(acc[i][0]);
        pre[(kh * 64 + rg + 16 * i) * PP + bg + 16] = f2sum(acc[i][1]);
      }
    }
    __syncthreads();

    // ---- gates + state (one (unit, batch) per thread)
    {
      float g0 = xv0 + pre[(0 * 16 + u) * PP + bw] + pre[(64 + 0 * 16 + u) * PP + bw];
      float g1 = xv1 + pre[(1 * 16 + u) * PP + bw] + pre[(64 + 1 * 16 + u) * PP + bw];
      float g2 = xv2 + pre[(2 * 16 + u) * PP + bw] + pre[(64 + 2 * 16 + u) * PP + bw];
      float g3 = xv3 + pre[(3 * 16 + u) * PP + bw] + pre[(64 + 3 * 16 + u) * PP + bw];
      float gi = fsigm(g0);
      float gf = fsigm(g1);
      float gg = ftanh(g2);
      float go = fsigm(g3);
      c = gf * c + gi * gg;
      float h = go * ftanh(c);
      __stcg(g_h + ((size_t)team * Tn + t) * Bn * Hn + (size_t)bw * Hn + unit, h);
      if (t == Tn - 1)
        out[(size_t)team * Bn * Hn + (size_t)bw * Hn + unit] = c;
    }
    __syncthreads();
    if (tid == 0) {
      asm volatile("fence.acq_rel.gpu;" ::: "memory");
      asm volatile("st.relaxed.gpu.global.b32 [%0], %1;"
                   :: "l"(my_hfl), "r"((unsigned)(t + 1)) : "memory");
    }

    // ---- xg production for layer team+1, t-1 (uses current z = h_{t-1})
    if (team < 3 && t >= 1) {
      xg_stream(t - 1);
      __syncthreads();
      if (tid == 0) {
        asm volatile("fence.acq_rel.gpu;" ::: "memory");
        asm volatile("st.relaxed.gpu.global.b32 [%0], %1;"
                     :: "l"(my_xfl), "r"((unsigned)t) : "memory");
      }
    }
  }

  // ---- epilogue: produce xg[team+1][2047] from h_2047
  if (team < 3) {
    if (tid < 32) {
      bool ok;
      do {
        unsigned v;
        asm volatile("ld.relaxed.gpu.global.b32 %0, [%1];"
                     : "=r"(v) : "l"(hfl + tid) : "memory");
        ok = (v >= (unsigned)Tn);
      } while (!__all_sync(0xffffffffu, ok));
      asm volatile("fence.acq_rel.gpu;" ::: "memory");
    }
    __syncthreads();
    issue_chunk(0);
    {
      const float4* h4 = reinterpret_cast<const float4*>(
          g_h + ((size_t)team * Tn + (Tn - 1)) * Bn * Hn);
#pragma unroll
      for (int i = 0; i < 8; i++) {
        int idx = tid + i * WTPB;
        int b = idx >> 7, jq = idx & 127;
        float4 v = __ldcg(h4 + idx);
        *reinterpret_cast<float4*>(zsh + b * ZPITCH + jq * 4) = v;
      }
    }
    __syncthreads();
    xg_stream(Tn - 1);
    __syncthreads();
    if (tid == 0) {
      asm volatile("fence.acq_rel.gpu;" ::: "memory");
      asm volatile("st.relaxed.gpu.global.b32 [%0], %1;"
                   :: "l"(my_xfl), "r"((unsigned)Tn) : "memory");
    }
  }
}

extern "C" void kernel_launch(void* const* d_in, const int* in_sizes, int n_in,
                              void* d_out, int out_size) {
  const float* x    = (const float*)d_in[0];
  const float* h0   = (const float*)d_in[1];
  const float* c0   = (const float*)d_in[2];
  const float* w_ih = (const float*)d_in[3];
  const float* w_hh = (const float*)d_in[4];
  const float* b_ih = (const float*)d_in[5];
  const float* b_hh = (const float*)d_in[6];
  float* out = (float*)d_out;

  cudaFuncSetAttribute(xg_gemm_kernel,
                       cudaFuncAttributeMaxDynamicSharedMemorySize, GEMM_SMEM);
  cudaFuncSetAttribute(lstm_wave_kernel,
                       cudaFuncAttributeMaxDynamicSharedMemorySize, WAVE_SMEM);

  // our launch #4 = wave kernel (ncu -s 5 captures it)
  init_kernel<<<1, 256>>>();
  xg_gemm_kernel<<<dim3(Tn / 4, Gn / TR), GT, GEMM_SMEM>>>(w_ih, b_ih, b_hh, x);
  init_kernel<<<1, 256>>>();
  lstm_wave_kernel<<<128, WTPB, WAVE_SMEM>>>(h0, c0, w_ih, w_hh, b_ih, b_hh, out);
}

// round 17
// speedup vs baseline: 1.1951x; 1.1951x over previous
#include <cuda_runtime.h>
#include <math.h>

#define Bn 32
#define Tn 2048
#define In 512
#define Hn 512
#define Ln 4
#define Gn 2048   // 4*H

// ---------------- phase A (layer-0 xg pre-GEMM) ----------------
#define GT 256
#define TR 128
#define TK 32
#define WPAD 132
#define ZPAD 132
#define GEMM_SMEM ((2*TK*WPAD + 2*TK*ZPAD) * 4)

// ---------------- wavefront kernel (R11 + per-warp xg streaming) ----------------
#define WTPB 512
#define WHP 512       // Whh smem pitch (broadcast loads -> no conflicts)
#define ZPITCH 516
#define PP 33         // pre pitch (bank-conflict-free gate reads)
#define XG_T 65536    // floats per (layer,t) block: 32cl * 32b * 64rows
// smem floats: Whh 64*512 | z 32*516 | pre 2*64*33 | wbuf 2*2048 | bsh 64
#define SM_WHH 0
#define SM_Z   (64*WHP)
#define SM_PRE (SM_Z + 32*ZPITCH)
#define SM_WBUF (SM_PRE + 2*64*PP)
#define SM_BSH (SM_WBUF + 2*2048)
#define WAVE_SMEM ((SM_BSH + 64) * 4)

// Static scratch
__device__ float g_xg[(size_t)Ln * Tn * XG_T];        // [l][t][cl][b][64]
__device__ float g_h[(size_t)Ln * Tn * Bn * Hn];      // [l][t][b][j]
__device__ unsigned g_flags[256];                     // [0:128) h, [128:256) xg

__global__ void init_kernel() {
  if (threadIdx.x < 256) g_flags[threadIdx.x] = 0u;
}

#define FMA2(acc, a, b) \
  asm("fma.rn.f32x2 %0, %1, %2, %0;" : "+l"(acc) : "l"(a), "l"(b))

__device__ __forceinline__ float f2sum(unsigned long long v) {
  unsigned lo = (unsigned)v, hi = (unsigned)(v >> 32);
  return __uint_as_float(lo) + __uint_as_float(hi);
}

__device__ __forceinline__ unsigned smem_u32(const void* p) {
  return (unsigned)__cvta_generic_to_shared(p);
}

// ============ Phase A (R11 scalar version): xg[0][t][cl][b][64] ============
__global__ void __launch_bounds__(GT, 2) xg_gemm_kernel(
    const float* __restrict__ W,
    const float* __restrict__ bih, const float* __restrict__ bhh,
    const float* __restrict__ x)
{
  extern __shared__ float sm[];
  float* Ws = sm;
  float* Zs = sm + 2 * TK * WPAD;

  const int tid = threadIdx.x;
  const int t0 = blockIdx.x * 4;
  const int r0 = blockIdx.y * TR;
  const int trow = tid >> 4;
  const int tcol = tid & 15;

  float acc[8][8];
#pragma unroll
  for (int i = 0; i < 8; i++)
#pragma unroll
    for (int j = 0; j < 8; j++) acc[i][j] = 0.f;

  float4 wr[4], zr[4];

  auto ldg_chunk = [&](int kc) {
#pragma unroll
    for (int j = 0; j < 4; j++) {
      int idx = tid * 4 + j;
      int row = idx >> 3, kq = idx & 7;
      wr[j] = *reinterpret_cast<const float4*>(W + (size_t)(r0 + row) * In + kc + kq * 4);
    }
#pragma unroll
    for (int j = 0; j < 4; j++) {
      int idx = tid * 4 + j;
      int ki = idx & 7, tt = (idx >> 3) & 3, b = idx >> 5;
      zr[j] = *reinterpret_cast<const float4*>(x + ((size_t)b * Tn + t0 + tt) * In + kc + ki * 4);
    }
  };

  auto sts_chunk = [&](int buf) {
    float* Wb = Ws + buf * TK * WPAD;
    float* Zb = Zs + buf * TK * ZPAD;
#pragma unroll
    for (int j = 0; j < 4; j++) {
      int idx = tid * 4 + j;
      int row = idx >> 3, kq = idx & 7;
      Wb[(kq * 4 + 0) * WPAD + row] = wr[j].x;
      Wb[(kq * 4 + 1) * WPAD + row] = wr[j].y;
      Wb[(kq * 4 + 2) * WPAD + row] = wr[j].z;
      Wb[(kq * 4 + 3) * WPAD + row] = wr[j].w;
    }
#pragma unroll
    for (int j = 0; j < 4; j++) {
      int idx = tid * 4 + j;
      int ki = idx & 7, tt = (idx >> 3) & 3, b = idx >> 5;
      Zb[(ki * 4 + 0) * ZPAD + tt * 32 + b] = zr[j].x;
      Zb[(ki * 4 + 1) * ZPAD + tt * 32 + b] = zr[j].y;
      Zb[(ki * 4 + 2) * ZPAD + tt * 32 + b] = zr[j].z;
      Zb[(ki * 4 + 3) * ZPAD + tt * 32 + b] = zr[j].w;
    }
  };

  auto compute = [&](int buf) {
    const float* Wb = Ws + buf * TK * WPAD;
    const float* Zb = Zs + buf * TK * ZPAD;
#pragma unroll 8
    for (int kk = 0; kk < TK; kk++) {
      float4 wa = *reinterpret_cast<const float4*>(Wb + kk * WPAD + trow * 8);
      float4 wb2 = *reinterpret_cast<const float4*>(Wb + kk * WPAD + trow * 8 + 4);
      float4 za = *reinterpret_cast<const float4*>(Zb + kk * ZPAD + tcol * 8);
      float4 zb2 = *reinterpret_cast<const float4*>(Zb + kk * ZPAD + tcol * 8 + 4);
      float w8[8] = {wa.x, wa.y, wa.z, wa.w, wb2.x, wb2.y, wb2.z, wb2.w};
      float z8[8] = {za.x, za.y, za.z, za.w, zb2.x, zb2.y, zb2.z, zb2.w};
#pragma unroll
      for (int i = 0; i < 8; i++)
#pragma unroll
        for (int j = 0; j < 8; j++)
          acc[i][j] = fmaf(w8[i], z8[j], acc[i][j]);
    }
  };

  const int NCH = In / TK;
  ldg_chunk(0);
  sts_chunk(0);
  __syncthreads();
  ldg_chunk(TK);
  for (int c = 0; c < NCH; c++) {
    int buf = c & 1;
    if (c + 1 < NCH) sts_chunk(buf ^ 1);
    if (c + 2 < NCH) ldg_chunk((c + 2) * TK);
    compute(buf);
    __syncthreads();
  }

  // epilogue: [cl][b][64] layout
#pragma unroll
  for (int i = 0; i < 8; i++) {
    int row = r0 + trow * 8 + i;
    float bv = __ldg(bih + row) + __ldg(bhh + row);
    int tt = tcol >> 2;
    int b0 = (tcol & 3) * 8;
    int q = row >> 9, rem = row & 511;
    int clr = rem >> 4, ur = rem & 15;
    float* dst = g_xg + (size_t)(t0 + tt) * XG_T + clr * 2048 + (q * 16 + ur);
#pragma unroll
    for (int j = 0; j < 8; j++)
      dst[(b0 + j) * 64] = acc[i][j] + bv;
  }
}

__device__ __forceinline__ float fsigm(float v) {
  return __fdividef(1.f, 1.f + __expf(-v));
}
// overflow-safe fast tanh (clamp; avoids -inf/inf NaN)
__device__ __forceinline__ float ftanh(float v) {
  v = fminf(15.f, fmaxf(-15.f, v));
  float e = __expf(-2.f * v);
  return __fdividef(1.f - e, 1.f + e);
}

// ============ Wavefront: 4 layer-teams x 32 CTAs, persistent ============
__global__ void __launch_bounds__(WTPB, 1) lstm_wave_kernel(
    const float* __restrict__ h0, const float* __restrict__ c0,
    const float* __restrict__ w_ih, const float* __restrict__ w_hh,
    const float* __restrict__ b_ih, const float* __restrict__ b_hh,
    float* __restrict__ out)
{
  extern __shared__ float smem[];
  float* Wsh = smem + SM_WHH;            // [64][512]
  float* zsh = smem + SM_Z;              // [32][516]  z[b][j]
  float* pre = smem + SM_PRE;            // [2][64][33]
  float* wbuf = smem + SM_WBUF;          // [2][16 warps][128] per-warp Wih slices
  float* bsh = smem + SM_BSH;            // [64]
  const unsigned wbuf_u32 = smem_u32(wbuf);

  const int tid = threadIdx.x;
  const int ct = blockIdx.x;
  const int team = ct >> 5;              // layer
  const int cl = ct & 31;
  // shared GEMM mapping (rec + xg)
  const int kh = tid >> 8;               // K-half
  const int rg = (tid >> 4) & 15;        // rows rg, +16, +32, +48
  const int bg = tid & 15;               // batches bg, bg+16
  // gates mapping: one (unit, batch) per thread
  const int u = tid & 15;                // unit 0..15
  const int bw = tid >> 4;               // batch 0..31
  const int unit = cl * 16 + u;
  // per-warp xg streaming identifiers
  const int wrp = tid >> 5;              // warp 0..15
  const int lane = tid & 31;
  const int rgA = (2 * wrp) & 15;        // even rg of this warp
  const int rd = rg & 1;                 // 0/1: this thread's row within pair

  // load Whh slice
  const float* Whh = w_hh + (size_t)team * Gn * Hn;
  for (int idx = tid; idx < 64 * 128; idx += WTPB) {
    int rr = idx >> 7, kk = idx & 127;
    int q = rr >> 4, uu = rr & 15;
    int grb = q * Hn + cl * 16 + uu;
    *reinterpret_cast<float4*>(Wsh + rr * WHP + kk * 4) =
        *reinterpret_cast<const float4*>(Whh + (size_t)grb * Hn + kk * 4);
  }
  float c = c0[(size_t)team * Bn * Hn + (size_t)bw * Hn + unit];

  const float* WihN = w_ih + (size_t)(team + 1) * Gn * In;
  if (team < 3 && tid < 64) {
    int grow = (tid >> 4) * Hn + cl * 16 + (tid & 15);
    bsh[tid] = __ldg(b_ih + (size_t)(team + 1) * Gn + grow) +
               __ldg(b_hh + (size_t)(team + 1) * Gn + grow);
  }

  unsigned* hfl = g_flags + team * 32;
  unsigned* xflp = g_flags + 128 + (team - 1) * 32 + cl;
  unsigned* my_hfl = g_flags + ct;
  unsigned* my_xfl = g_flags + 128 + ct;

  // per-warp slice fetch: this warp's 8 rows x 16 K-floats of chunk cidx.
  // lane L: row_idx = L>>2 (0..7), quad = L&3. row = rgA + (row_idx&1) + 16*(row_idx>>1)
  auto issue_chunk = [&](int cidx) {
    int row_idx = lane >> 2;
    int quad = lane & 3;
    int row = rgA + (row_idx & 1) + 16 * (row_idx >> 1);
    int grow = (row >> 4) * Hn + cl * 16 + (row & 15);
    const char* src = reinterpret_cast<const char*>(
        WihN + (size_t)grow * In + kh * 256 + cidx * 16 + quad * 4);
    unsigned dst = wbuf_u32 +
        (unsigned)(((cidx & 1) * 2048 + wrp * 128 + row_idx * 16 + quad * 4) * 4);
    asm volatile("cp.async.cg.shared.global [%0], [%1], 16;" :: "r"(dst), "l"(src));
    asm volatile("cp.async.commit_group;" ::: "memory");
  };

  // stream xg[team+1][tt] from current z; chunks 0,1 issued at step top.
  // Per-warp pipeline: no block syncs in the chunk loop.
  auto xg_stream = [&](int tt) {
    unsigned long long ax[4][2];
#pragma unroll
    for (int i = 0; i < 4; i++) { ax[i][0] = 0ull; ax[i][1] = 0ull; }
#pragma unroll 1
    for (int cc = 0; cc < 16; cc++) {
      if (cc == 15) asm volatile("cp.async.wait_group 0;" ::: "memory");
      else          asm volatile("cp.async.wait_group 1;" ::: "memory");
      __syncwarp();                      // whole 512B warp slice visible
      const float* wc = wbuf + (cc & 1) * 2048 + wrp * 128;
      const float* zp0 = zsh + bg * ZPITCH + kh * 256 + cc * 16;
      const float* zp1 = zp0 + 16 * ZPITCH;
#pragma unroll
      for (int j = 0; j < 16; j += 4) {
        ulonglong2 z0 = *reinterpret_cast<const ulonglong2*>(zp0 + j);
        ulonglong2 z1 = *reinterpret_cast<const ulonglong2*>(zp1 + j);
#pragma unroll
        for (int i = 0; i < 4; i++) {
          ulonglong2 w = *reinterpret_cast<const ulonglong2*>(wc + (rd + 2 * i) * 16 + j);
          FMA2(ax[i][0], w.x, z0.x); FMA2(ax[i][0], w.y, z0.y);
          FMA2(ax[i][1], w.x, z1.x); FMA2(ax[i][1], w.y, z1.y);
        }
      }
      __syncwarp();                      // slice reads done before slot reuse
      if (cc + 2 < 16) issue_chunk(cc + 2);
    }
#pragma unroll
    for (int i = 0; i < 4; i++) {
      pre[(kh * 64 + rg + 16 * i) * PP + bg] = f2sum(ax[i][0]);
      pre[(kh * 64 + rg + 16 * i) * PP + bg + 16] = f2sum(ax[i][1]);
    }
    __syncthreads();
    {
      int b = tid >> 4, r4 = (tid & 15) * 4;
      float4 o;
      float* op = reinterpret_cast<float*>(&o);
#pragma unroll
      for (int i = 0; i < 4; i++)
        op[i] = pre[(r4 + i) * PP + b] + pre[(64 + r4 + i) * PP + b] + bsh[r4 + i];
      size_t xbase = ((size_t)(team + 1) * Tn + tt) * XG_T + cl * 2048;
      __stcg(reinterpret_cast<float4*>(g_xg + xbase + b * 64 + r4), o);
    }
  };

  float xv0, xv1, xv2, xv3;

  for (int t = 0; t < Tn; t++) {
    // per-warp prefetch of Wih chunks 0,1 (static weights; overlaps everything)
    if (team < 3 && t >= 1) { issue_chunk(0); issue_chunk(1); }

    // ---- wait: own-team h flags >= t; upstream xg flag >= t+1
    if (t > 0 || team > 0) {
      if (tid < 32) {
        bool ok;
        do {
          ok = true;
          if (t > 0) {
            unsigned v;
            asm volatile("ld.relaxed.gpu.global.b32 %0, [%1];"
                         : "=r"(v) : "l"(hfl + tid) : "memory");
            ok &= (v >= (unsigned)t);
          }
          if (team > 0) {
            unsigned v2;
            asm volatile("ld.relaxed.gpu.global.b32 %0, [%1];"
                         : "=r"(v2) : "l"(xflp) : "memory");
            ok &= (v2 >= (unsigned)(t + 1));
          }
        } while (!__all_sync(0xffffffffu, ok));
        asm volatile("fence.acq_rel.gpu;" ::: "memory");
      }
      __syncthreads();
    }

    // ---- stage z[b][j] = h_{t-1} (pure coalesced copy)
    {
      const float4* h4 = (t == 0)
          ? reinterpret_cast<const float4*>(h0 + (size_t)team * Bn * Hn)
          : reinterpret_cast<const float4*>(
                g_h + ((size_t)team * Tn + (t - 1)) * Bn * Hn);
#pragma unroll
      for (int i = 0; i < 8; i++) {
        int idx = tid + i * WTPB;
        int b = idx >> 7, jq = idx & 127;
        float4 v = __ldcg(h4 + idx);
        *reinterpret_cast<float4*>(zsh + b * ZPITCH + jq * 4) = v;
      }
    }
    {
      const float* xp = g_xg + ((size_t)team * Tn + t) * XG_T + cl * 2048 + bw * 64 + u;
      xv0 = __ldcg(xp);
      xv1 = __ldcg(xp + 16);
      xv2 = __ldcg(xp + 32);
      xv3 = __ldcg(xp + 48);
    }
    __syncthreads();

    // ---- rec GEMM (f32x2): 4 rows x 2 batches x 256 K per thread
    {
      const float* wr = Wsh + rg * WHP + kh * 256;
      const float* zp = zsh + bg * ZPITCH + kh * 256;
      unsigned long long acc[4][2];
#pragma unroll
      for (int i = 0; i < 4; i++) { acc[i][0] = 0ull; acc[i][1] = 0ull; }
#pragma unroll 4
      for (int k = 0; k < 256; k += 4) {
        ulonglong2 z0 = *reinterpret_cast<const ulonglong2*>(zp + k);
        ulonglong2 z1 = *reinterpret_cast<const ulonglong2*>(zp + 16 * ZPITCH + k);
#pragma unroll
        for (int i = 0; i < 4; i++) {
          ulonglong2 w = *reinterpret_cast<const ulonglong2*>(wr + i * 16 * WHP + k);
          FMA2(acc[i][0], w.x, z0.x); FMA2(acc[i][0], w.y, z0.y);
          FMA2(acc[i][1], w.x, z1.x); FMA2(acc[i][1], w.y, z1.y);
        }
      }
#pragma unroll
      for (int i = 0; i < 4; i++) {
        pre[(kh * 64 + rg + 16 * i) * PP + bg] = f2sum(acc[i][0]);
        pre[(kh * 64 + rg + 16 * i) * PP + bg + 16] = f2sum(acc[i][1]);
      }
    }
    __syncthreads();

    // ---- gates + state (one (unit, batch) per thread)
    {
      float g0 = xv0 + pre[(0 * 16 + u) * PP + bw] + pre[(64 + 0 * 16 + u) * PP + bw];
      float g1 = xv1 + pre[(1 * 16 + u) * PP + bw] + pre[(64 + 1 * 16 + u) * PP + bw];
      float g2 = xv2 + pre[(2 * 16 + u) * PP + bw] + pre[(64 + 2 * 16 + u) * PP + bw];
      float g3 = xv3 + pre[(3 * 16 + u) * PP + bw] + pre[(64 + 3 * 16 + u) * PP + bw];
      float gi = fsigm(g0);
      float gf = fsigm(g1);
      float gg = ftanh(g2);
      float go = fsigm(g3);
      c = gf * c + gi * gg;
      float h = go * ftanh(c);
      __stcg(g_h + ((size_t)team * Tn + t) * Bn * Hn + (size_t)bw * Hn + unit, h);
      if (t == Tn - 1)
        out[(size_t)team * Bn * Hn + (size_t)bw * Hn + unit] = c;
    }
    __syncthreads();
    if (tid == 0) {
      asm volatile("fence.acq_rel.gpu;" ::: "memory");
      asm volatile("st.relaxed.gpu.global.b32 [%0], %1;"
                   :: "l"(my_hfl), "r"((unsigned)(t + 1)) : "memory");
    }

    // ---- xg production for layer team+1, t-1 (uses current z = h_{t-1})
    if (team < 3 && t >= 1) {
      xg_stream(t - 1);
      __syncthreads();
      if (tid == 0) {
        asm volatile("fence.acq_rel.gpu;" ::: "memory");
        asm volatile("st.relaxed.gpu.global.b32 [%0], %1;"
                     :: "l"(my_xfl), "r"((unsigned)t) : "memory");
      }
    }
  }

  // ---- epilogue: produce xg[team+1][2047] from h_2047
  if (team < 3) {
    if (tid < 32) {
      bool ok;
      do {
        unsigned v;
        asm volatile("ld.relaxed.gpu.global.b32 %0, [%1];"
                     : "=r"(v) : "l"(hfl + tid) : "memory");
        ok = (v >= (unsigned)Tn);
      } while (!__all_sync(0xffffffffu, ok));
      asm volatile("fence.acq_rel.gpu;" ::: "memory");
    }
    __syncthreads();
    issue_chunk(0);
    issue_chunk(1);
    {
      const float4* h4 = reinterpret_cast<const float4*>(
          g_h + ((size_t)team * Tn + (Tn - 1)) * Bn * Hn);
#pragma unroll
      for (int i = 0; i < 8; i++) {
        int idx = tid + i * WTPB;
        int b = idx >> 7, jq = idx & 127;
        float4 v = __ldcg(h4 + idx);
        *reinterpret_cast<float4*>(zsh + b * ZPITCH + jq * 4) = v;
      }
    }
    __syncthreads();
    xg_stream(Tn - 1);
    __syncthreads();
    if (tid == 0) {
      asm volatile("fence.acq_rel.gpu;" ::: "memory");
      asm volatile("st.relaxed.gpu.global.b32 [%0], %1;"
                   :: "l"(my_xfl), "r"((unsigned)Tn) : "memory");
    }
  }
}

extern "C" void kernel_launch(void* const* d_in, const int* in_sizes, int n_in,
                              void* d_out, int out_size) {
  const float* x    = (const float*)d_in[0];
  const float* h0   = (const float*)d_in[1];
  const float* c0   = (const float*)d_in[2];
  const float* w_ih = (const float*)d_in[3];
  const float* w_hh = (const float*)d_in[4];
  const float* b_ih = (const float*)d_in[5];
  const float* b_hh = (const float*)d_in[6];
  float* out = (float*)d_out;

  cudaFuncSetAttribute(xg_gemm_kernel,
                       cudaFuncAttributeMaxDynamicSharedMemorySize, GEMM_SMEM);
  cudaFuncSetAttribute(lstm_wave_kernel,
                       cudaFuncAttributeMaxDynamicSharedMemorySize, WAVE_SMEM);

  // our launch #4 = wave kernel (ncu -s 5 captures it)
  init_kernel<<<1, 256>>>();
  xg_gemm_kernel<<<dim3(Tn / 4, Gn / TR), GT, GEMM_SMEM>>>(w_ih, b_ih, b_hh, x);
  init_kernel<<<1, 256>>>();
  lstm_wave_kernel<<<128, WTPB, WAVE_SMEM>>>(h0, c0, w_ih, w_hh, b_ih, b_hh, out);
}